// round 6
// baseline (speedup 1.0000x reference)
#include <cuda_runtime.h>
#include <cstdint>

// H100SmartEmbedding: out[r, :] = concat(price[0], size[0], exch[r%3], pair[r%7],
//                                        level[r%15], time[r%31]), 6 x 128 fp32.
//
// Period trick: lcm(3,7,15,31) = 3255. Any row stride that's a multiple of
// 3255 preserves all four residues, so each block sees ONE set of table rows:
// one LDG per thread for the whole kernel, then a pure STG.128 stream.
//
// R6 probe: same geometry as R4 (192 thr, SPLIT=6 — best measured DRAM%),
// but DEFAULT stores instead of __stcs. Theory: .cs evict-first forces eager
// L2 writeback and defeats dirty-line batching toward the memory controller;
// default caching lets L2 absorb/schedule the write stream (we measured ~60MB
// retiring post-kernel). Unroll 8 for extra outstanding-store depth.

#define PERIOD 3255
#define SPLIT  6

__global__ void __launch_bounds__(192)
smart_embedding_kernel(const float4* __restrict__ price,
                       const float4* __restrict__ size_,
                       const float4* __restrict__ exch,
                       const float4* __restrict__ pair,
                       const float4* __restrict__ level,
                       const float4* __restrict__ timew,
                       float4* __restrict__ out,
                       int num_features)
{
    const int t   = threadIdx.x;   // 0..191
    const int sec = t >> 5;        // warp id = section id
    const int c4  = t & 31;        // float4 column within the 128-float section

    const int residue = blockIdx.x % PERIOD;  // const-mod -> mul/shift, once/block
    const int chunk   = blockIdx.x / PERIOD;  // 0..SPLIT-1

    // Block-constant table row per section: every row this block writes is
    // ≡ residue (mod 3255), hence fixed residues mod 3/7/15/31.
    float4 v;
    if (sec == 0) {
        v = __ldg(&price[c4]);
    } else if (sec == 1) {
        v = __ldg(&size_[c4]);
    } else if (sec == 2) {
        v = __ldg(&exch[(residue % 3) * 32 + c4]);
    } else if (sec == 3) {
        v = __ldg(&pair[(residue % 7) * 32 + c4]);
    } else if (sec == 4) {
        v = __ldg(&level[(residue % 15) * 32 + c4]);
    } else {
        v = __ldg(&timew[(residue % 31) * 32 + c4]);
    }

    // Rows handled by this block: residue + chunk*PERIOD, stepping SPLIT*PERIOD.
    int r = residue + chunk * PERIOD;
    if (r >= num_features) return;

    const int    rstride = SPLIT * PERIOD;
    const size_t step    = (size_t)rstride * 192;
    float4* p = out + (size_t)r * 192 + t;

    // Pure store stream; DEFAULT caching (let L2 buffer and batch writebacks).
    #pragma unroll 8
    for (; r + 7 * rstride < num_features; r += 8 * rstride) {
        p[0]        = v;
        p[step]     = v;
        p[2 * step] = v;
        p[3 * step] = v;
        p[4 * step] = v;
        p[5 * step] = v;
        p[6 * step] = v;
        p[7 * step] = v;
        p += 8 * step;
    }
    for (; r < num_features; r += rstride) {
        *p = v;
        p += step;
    }
}

extern "C" void kernel_launch(void* const* d_in, const int* in_sizes, int n_in,
                              void* d_out, int out_size)
{
    const float4* price = (const float4*)d_in[0];
    const float4* size_ = (const float4*)d_in[1];
    const float4* exch  = (const float4*)d_in[2];
    const float4* pair  = (const float4*)d_in[3];
    const float4* level = (const float4*)d_in[4];
    const float4* timew = (const float4*)d_in[5];
    float4* out = (float4*)d_out;

    // num_features lives in device memory (d_in[6]); deriving it host-side
    // from out_size keeps kernel_launch graph-capturable.
    const int num_features = out_size / 768;

    smart_embedding_kernel<<<PERIOD * SPLIT, 192>>>(price, size_, exch, pair,
                                                    level, timew, out,
                                                    num_features);
}

// round 7
// speedup vs baseline: 1.0121x; 1.0121x over previous
#include <cuda_runtime.h>
#include <cstdint>

// H100SmartEmbedding: out[r, :] = concat(price[0], size[0], exch[r%3], pair[r%7],
//                                        level[r%15], time[r%31]), 6 x 128 fp32.
//
// Period trick: lcm(3,7,15,31) = 3255. Any row stride that's a multiple of
// 3255 preserves all four residues, so each block sees ONE set of table rows:
// one LDG per thread for the whole kernel, then a pure STG.128 stream.
//
// R7: revert to best-measured config (R4: 192thr, SPLIT=6, __stcs, unroll 4;
// 58.1us, DRAM 76%). Probes R5 (pair blocks) and R6 (default caching) were
// neutral/negative -> ~6.0 TB/s is the DRAM write-stream ceiling. Only delta
// vs R4: 2D grid (x=residue, y=chunk) removes the per-block div/mod pair.

#define PERIOD 3255
#define SPLIT  6

__global__ void __launch_bounds__(192)
smart_embedding_kernel(const float4* __restrict__ price,
                       const float4* __restrict__ size_,
                       const float4* __restrict__ exch,
                       const float4* __restrict__ pair,
                       const float4* __restrict__ level,
                       const float4* __restrict__ timew,
                       float4* __restrict__ out,
                       int num_features)
{
    const int t   = threadIdx.x;   // 0..191
    const int sec = t >> 5;        // warp id = section id
    const int c4  = t & 31;        // float4 column within the 128-float section

    const int residue = blockIdx.x;   // 0..PERIOD-1  (no div/mod needed)
    const int chunk   = blockIdx.y;   // 0..SPLIT-1

    // Block-constant table row per section: every row this block writes is
    // ≡ residue (mod 3255), hence fixed residues mod 3/7/15/31.
    float4 v;
    if (sec == 0) {
        v = __ldg(&price[c4]);
    } else if (sec == 1) {
        v = __ldg(&size_[c4]);
    } else if (sec == 2) {
        v = __ldg(&exch[(residue % 3) * 32 + c4]);
    } else if (sec == 3) {
        v = __ldg(&pair[(residue % 7) * 32 + c4]);
    } else if (sec == 4) {
        v = __ldg(&level[(residue % 15) * 32 + c4]);
    } else {
        v = __ldg(&timew[(residue % 31) * 32 + c4]);
    }

    // Rows handled by this block: residue + chunk*PERIOD, stepping SPLIT*PERIOD.
    int r = residue + chunk * PERIOD;
    if (r >= num_features) return;

    const int    rstride = SPLIT * PERIOD;
    const size_t step    = (size_t)rstride * 192;
    float4* p = out + (size_t)r * 192 + t;

    // Pure store stream; .cs (evict-first) matched or beat default in probes.
    #pragma unroll 4
    for (; r + 3 * rstride < num_features; r += 4 * rstride) {
        __stcs(p, v);
        __stcs(p + step, v);
        __stcs(p + 2 * step, v);
        __stcs(p + 3 * step, v);
        p += 4 * step;
    }
    for (; r < num_features; r += rstride) {
        __stcs(p, v);
        p += step;
    }
}

extern "C" void kernel_launch(void* const* d_in, const int* in_sizes, int n_in,
                              void* d_out, int out_size)
{
    const float4* price = (const float4*)d_in[0];
    const float4* size_ = (const float4*)d_in[1];
    const float4* exch  = (const float4*)d_in[2];
    const float4* pair  = (const float4*)d_in[3];
    const float4* level = (const float4*)d_in[4];
    const float4* timew = (const float4*)d_in[5];
    float4* out = (float4*)d_out;

    // num_features lives in device memory (d_in[6]); deriving it host-side
    // from out_size keeps kernel_launch graph-capturable.
    const int num_features = out_size / 768;

    dim3 grid(PERIOD, SPLIT, 1);
    smart_embedding_kernel<<<grid, 192>>>(price, size_, exch, pair,
                                          level, timew, out, num_features);
}

// round 8
// speedup vs baseline: 1.0166x; 1.0044x over previous
#include <cuda_runtime.h>
#include <cstdint>

// H100SmartEmbedding: out[r, :] = concat(price[0], size[0], exch[r%3], pair[r%7],
//                                        level[r%15], time[r%31]), 6 x 128 fp32.
//
// Period trick: lcm(3,7,15,31) = 3255. Work in ROW PAIRS: pairs p ≡ residue
// (mod 3255) -> rows 2p,2p+1 have block-constant residues mod 3/7/15/31, so
// each thread loads its 32B table chunk ONCE; mainloop is a pure store stream.
//
// R8 probe: sm_103a 256-bit stores (st.global.cs.v8.f32 -> STG.256).
// 192 threads x 32B = one full 6KB row-pair per block-iteration. Halves store
// instruction / wavefront count vs STG.128. DRAM-ceiling model predicts
// neutral; this is the last untried store-path lever.

#define PERIOD 3255
#define SPLITP 6   // splits per residue class (over pairs) -> grid 19530

__global__ void __launch_bounds__(192)
smart_embedding_kernel(const float4* __restrict__ price,
                       const float4* __restrict__ size_,
                       const float4* __restrict__ exch,
                       const float4* __restrict__ pair,
                       const float4* __restrict__ level,
                       const float4* __restrict__ timew,
                       float* __restrict__ out,
                       int num_features)
{
    const int t   = threadIdx.x;     // 0..191
    const int rip = t / 96;          // row-in-pair: 0 or 1
    const int u   = t % 96;          // chunk within row (96 x 8 floats = 768)
    const int sec = u >> 4;          // section 0..5
    const int c8  = u & 15;          // 32B chunk within the 128-float section

    const int residue = blockIdx.x;  // pair residue, 0..PERIOD-1
    const int chunk   = blockIdx.y;  // 0..SPLITP-1

    // Row this warp-lane serves at pair p: r = 2p + rip, p ≡ residue (mod 3255)
    // -> r ≡ 2*residue + rip (mod 3255): table rows are block-constant.
    const int rbase = 2 * residue + rip;

    // One-time 32B table load per thread (tables: 31.75KB total, L1/L2-hot).
    const float4* src;
    if (sec == 0) {
        src = price + c8 * 2;
    } else if (sec == 1) {
        src = size_ + c8 * 2;
    } else if (sec == 2) {
        src = exch + (rbase % 3) * 32 + c8 * 2;
    } else if (sec == 3) {
        src = pair + (rbase % 7) * 32 + c8 * 2;
    } else if (sec == 4) {
        src = level + (rbase % 15) * 32 + c8 * 2;
    } else {
        src = timew + (rbase % 31) * 32 + c8 * 2;
    }
    const float4 v0 = __ldg(src);
    const float4 v1 = __ldg(src + 1);

    // Pairs handled by this block: residue + chunk*PERIOD, step SPLITP*PERIOD.
    const int num_pairs = num_features >> 1;
    int p = residue + chunk * PERIOD;
    if (p >= num_pairs) return;

    const int    pstride = SPLITP * PERIOD;
    const size_t stepf   = (size_t)pstride * 1536;   // floats per pair-stride
    float* ptr = out + (size_t)p * 1536 + t * 8;

    // Pure 256-bit store stream; .cs = evict-first for write-once data.
    #pragma unroll 4
    for (; p < num_pairs; p += pstride) {
        asm volatile(
            "st.global.cs.v8.f32 [%0], {%1, %2, %3, %4, %5, %6, %7, %8};"
            :: "l"(ptr),
               "f"(v0.x), "f"(v0.y), "f"(v0.z), "f"(v0.w),
               "f"(v1.x), "f"(v1.y), "f"(v1.z), "f"(v1.w)
            : "memory");
        ptr += stepf;
    }
}

// Tail for odd num_features (not hit for this dataset: 131072 is even).
__global__ void __launch_bounds__(192)
smart_embedding_tail(const float4* __restrict__ price,
                     const float4* __restrict__ size_,
                     const float4* __restrict__ exch,
                     const float4* __restrict__ pair,
                     const float4* __restrict__ level,
                     const float4* __restrict__ timew,
                     float4* __restrict__ out,
                     int row)
{
    const int t   = threadIdx.x;
    const int sec = t >> 5;
    const int c4  = t & 31;
    float4 v;
    if (sec == 0)      v = __ldg(&price[c4]);
    else if (sec == 1) v = __ldg(&size_[c4]);
    else if (sec == 2) v = __ldg(&exch[(row % 3) * 32 + c4]);
    else if (sec == 3) v = __ldg(&pair[(row % 7) * 32 + c4]);
    else if (sec == 4) v = __ldg(&level[(row % 15) * 32 + c4]);
    else               v = __ldg(&timew[(row % 31) * 32 + c4]);
    out[(size_t)row * 192 + t] = v;
}

extern "C" void kernel_launch(void* const* d_in, const int* in_sizes, int n_in,
                              void* d_out, int out_size)
{
    const float4* price = (const float4*)d_in[0];
    const float4* size_ = (const float4*)d_in[1];
    const float4* exch  = (const float4*)d_in[2];
    const float4* pair  = (const float4*)d_in[3];
    const float4* level = (const float4*)d_in[4];
    const float4* timew = (const float4*)d_in[5];

    // num_features lives in device memory (d_in[6]); deriving it host-side
    // from out_size keeps kernel_launch graph-capturable.
    const int num_features = out_size / 768;

    dim3 grid(PERIOD, SPLITP, 1);
    smart_embedding_kernel<<<grid, 192>>>(price, size_, exch, pair, level,
                                          timew, (float*)d_out, num_features);
    if (num_features & 1) {
        smart_embedding_tail<<<1, 192>>>(price, size_, exch, pair, level,
                                         timew, (float4*)d_out,
                                         num_features - 1);
    }
}